// round 7
// baseline (speedup 1.0000x reference)
#include <cuda_runtime.h>

#define N_IMG 8
#define H 32
#define W 32
#define CIN 32
#define COUT 64
#define HO 30
#define WO 30
#define NPIX (N_IMG*HO*WO)       // 7200
#define PDIM (3*3*CIN)           // 288

typedef unsigned long long u64;

// Scratch (device globals: no allocation allowed in kernel_launch)
// g_vq: per element {vx,vx,vy,vy} pre-splatted for f32x2 (16B/element, 4MB)
__device__ __align__(16) float4 g_vq[N_IMG*H*W*CIN];
__device__ __align__(16) float  g_ek1[PDIM*COUT];     // exp(k1), [p][cout]
__device__ __align__(16) float  g_ek2[PDIM*COUT];     // exp(k2), [p][cout]

#define NV4 (N_IMG*H*W*CIN/4)    // 65536 float4 elements of x
#define VBLOCKS (NV4/256)        // 256
#define WBLOCKS ((PDIM*COUT + 255)/256)  // 72

// packed multiply (f32x2), scalar max into two accumulators.
// mov.b64 unpack is register-pair aliasing; ptxas elides it.
__device__ __forceinline__ void mulmax(u64 v, u64 w, float& a0, float& a1) {
    float lo, hi;
    asm("{\n\t"
        ".reg .b64 t;\n\t"
        "mul.rn.f32x2 t, %2, %3;\n\t"
        "mov.b64 {%0, %1}, t;\n\t"
        "}" : "=f"(lo), "=f"(hi) : "l"(v), "l"(w));
    a0 = fmaxf(a0, lo);
    a1 = fmaxf(a1, hi);
}

// ---------------------------------------------------------------------------
// Fused prep:
//   blocks [0,VBLOCKS):  per input float x -> float4 {vx,vx,vy,vy}
//   blocks [VBLOCKS, VBLOCKS+WBLOCKS): exp(weights)
// ---------------------------------------------------------------------------
__global__ void prep(const float* __restrict__ x,
                     const float* __restrict__ k1,
                     const float* __restrict__ k2) {
    const int b = blockIdx.x;
    if (b < VBLOCKS) {
        const int e4 = b*256 + threadIdx.x;          // float4 index into x
        const float4 xv = reinterpret_cast<const float4*>(x)[e4];
        float4* vp = g_vq + e4*4;
        const float a0 = fmaxf(xv.x, 0.1f), b0 = fmaxf(-xv.x, 0.1f);
        const float a1 = fmaxf(xv.y, 0.1f), b1 = fmaxf(-xv.y, 0.1f);
        const float a2 = fmaxf(xv.z, 0.1f), b2 = fmaxf(-xv.z, 0.1f);
        const float a3 = fmaxf(xv.w, 0.1f), b3 = fmaxf(-xv.w, 0.1f);
        vp[0] = make_float4(a0, a0, b0, b0);
        vp[1] = make_float4(a1, a1, b1, b1);
        vp[2] = make_float4(a2, a2, b2, b2);
        vp[3] = make_float4(a3, a3, b3, b3);
    } else {
        const int i = (b - VBLOCKS)*256 + threadIdx.x;
        if (i < PDIM*COUT) {
            g_ek1[i] = expf(k1[i]);
            g_ek2[i] = expf(k2[i]);
        }
    }
}

// ---------------------------------------------------------------------------
// Main: CTA = 64 threads = 2 warps (k-split), covering 4 pixels x 64 couts.
//   lane: cg = l&15 (4 couts), pp = l>>4 (pixel-pair 0/1)
//   each LANE register-blocks 2 pixels (qa = base+2*pp, qb = qa+1)
//   warp w handles k in [48w, 48w+48) of each kernel row.
// Per warp-iter: 2 LDG.128 (v quads, broadcast) + 2 LDG.128 (w, reused for
//   both pixels) + 16 MUL.f32x2 + 32 FMNMX  -> 52 slots / 64 results.
// ---------------------------------------------------------------------------
__global__ void __launch_bounds__(64, 13)
morph_main(const float* __restrict__ bias, float* __restrict__ out) {
    __shared__ float4 s_red[32][8];

    const int t    = threadIdx.x;
    const int lane = t & 31;
    const int wrp  = t >> 5;      // 0 or 1: k-half
    const int cg   = lane & 15;   // cout group (4 couts)
    const int pp   = lane >> 4;   // pixel-pair 0/1
    const int c0   = cg * 4;

    const int qa = blockIdx.x*4 + pp*2;   // flat pixels qa, qa+1
    const int qb = qa + 1;

    const int na  = qa / (HO*WO);
    const int ra  = qa - na*(HO*WO);
    const int hoa = ra / WO;
    const int woa = ra - hoa*WO;
    const int nb  = qb / (HO*WO);
    const int rb  = qb - nb*(HO*WO);
    const int hob = rb / WO;
    const int wob = rb - hob*WO;

    const ulonglong2* __restrict__ va_base =
        reinterpret_cast<const ulonglong2*>(g_vq) + ((na*H + hoa)*W + woa)*CIN;
    const ulonglong2* __restrict__ vb_base =
        reinterpret_cast<const ulonglong2*>(g_vq) + ((nb*H + hob)*W + wob)*CIN;
    const ulonglong2* __restrict__ w1p = reinterpret_cast<const ulonglong2*>(g_ek1) + cg;
    const ulonglong2* __restrict__ w2p = reinterpret_cast<const ulonglong2*>(g_ek2) + cg;

    const int klo = wrp * 48;

    float a11[4], a12[4], a21[4], a22[4];   // pixel qa
    float b11[4], b12[4], b21[4], b22[4];   // pixel qb
    #pragma unroll
    for (int k = 0; k < 4; k++) {
        a11[k]=0.f; a12[k]=0.f; a21[k]=0.f; a22[k]=0.f;
        b11[k]=0.f; b12[k]=0.f; b21[k]=0.f; b22[k]=0.f;
    }

    #pragma unroll 1
    for (int i = 0; i < 3; i++) {
        const ulonglong2* __restrict__ vpa = va_base + i*(W*CIN) + klo;
        const ulonglong2* __restrict__ vpb = vb_base + i*(W*CIN) + klo;
        const ulonglong2* __restrict__ aw1 = w1p + (i*96 + klo)*16;
        const ulonglong2* __restrict__ aw2 = w2p + (i*96 + klo)*16;

        #pragma unroll 4
        for (int k = 0; k < 48; k++) {
            const ulonglong2 va = __ldg(vpa + k);   // {vxx, vyy} pixel a
            const ulonglong2 vb = __ldg(vpb + k);   // {vxx, vyy} pixel b
            const ulonglong2 w1 = __ldg(aw1 + k*16);
            const ulonglong2 w2 = __ldg(aw2 + k*16);
            mulmax(va.x, w1.x, a11[0], a11[1]);
            mulmax(va.x, w1.y, a11[2], a11[3]);
            mulmax(va.x, w2.x, a12[0], a12[1]);
            mulmax(va.x, w2.y, a12[2], a12[3]);
            mulmax(va.y, w1.x, a21[0], a21[1]);
            mulmax(va.y, w1.y, a21[2], a21[3]);
            mulmax(va.y, w2.x, a22[0], a22[1]);
            mulmax(va.y, w2.y, a22[2], a22[3]);
            mulmax(vb.x, w1.x, b11[0], b11[1]);
            mulmax(vb.x, w1.y, b11[2], b11[3]);
            mulmax(vb.x, w2.x, b12[0], b12[1]);
            mulmax(vb.x, w2.y, b12[2], b12[3]);
            mulmax(vb.y, w1.x, b21[0], b21[1]);
            mulmax(vb.y, w1.y, b21[2], b21[3]);
            mulmax(vb.y, w2.x, b22[0], b22[1]);
            mulmax(vb.y, w2.y, b22[2], b22[3]);
        }
    }

    // Cross-warp (k-half) max-combine: warp 1 publishes, warp 0 reduces+stores.
    if (wrp == 1) {
        s_red[lane][0] = make_float4(a11[0], a11[1], a11[2], a11[3]);
        s_red[lane][1] = make_float4(a12[0], a12[1], a12[2], a12[3]);
        s_red[lane][2] = make_float4(a21[0], a21[1], a21[2], a21[3]);
        s_red[lane][3] = make_float4(a22[0], a22[1], a22[2], a22[3]);
        s_red[lane][4] = make_float4(b11[0], b11[1], b11[2], b11[3]);
        s_red[lane][5] = make_float4(b12[0], b12[1], b12[2], b12[3]);
        s_red[lane][6] = make_float4(b21[0], b21[1], b21[2], b21[3]);
        s_red[lane][7] = make_float4(b22[0], b22[1], b22[2], b22[3]);
    }
    __syncthreads();
    if (wrp == 0) {
        const float4 bv = *reinterpret_cast<const float4*>(bias + c0);

        {
            const float4 o11 = s_red[lane][0], o12 = s_red[lane][1];
            const float4 o21 = s_red[lane][2], o22 = s_red[lane][3];
            float4 res;
            res.x = fmaxf(a11[0],o11.x) - fmaxf(a12[0],o12.x)
                  - fmaxf(a21[0],o21.x) + fmaxf(a22[0],o22.x) + bv.x;
            res.y = fmaxf(a11[1],o11.y) - fmaxf(a12[1],o12.y)
                  - fmaxf(a21[1],o21.y) + fmaxf(a22[1],o22.y) + bv.y;
            res.z = fmaxf(a11[2],o11.z) - fmaxf(a12[2],o12.z)
                  - fmaxf(a21[2],o21.z) + fmaxf(a22[2],o22.z) + bv.z;
            res.w = fmaxf(a11[3],o11.w) - fmaxf(a12[3],o12.w)
                  - fmaxf(a21[3],o21.w) + fmaxf(a22[3],o22.w) + bv.w;
            *reinterpret_cast<float4*>(out + (size_t)qa*COUT + c0) = res;
        }
        {
            const float4 o11 = s_red[lane][4], o12 = s_red[lane][5];
            const float4 o21 = s_red[lane][6], o22 = s_red[lane][7];
            float4 res;
            res.x = fmaxf(b11[0],o11.x) - fmaxf(b12[0],o12.x)
                  - fmaxf(b21[0],o21.x) + fmaxf(b22[0],o22.x) + bv.x;
            res.y = fmaxf(b11[1],o11.y) - fmaxf(b12[1],o12.y)
                  - fmaxf(b21[1],o21.y) + fmaxf(b22[1],o22.y) + bv.y;
            res.z = fmaxf(b11[2],o11.z) - fmaxf(b12[2],o12.z)
                  - fmaxf(b21[2],o21.z) + fmaxf(b22[2],o22.z) + bv.z;
            res.w = fmaxf(b11[3],o11.w) - fmaxf(b12[3],o12.w)
                  - fmaxf(b21[3],o21.w) + fmaxf(b22[3],o22.w) + bv.w;
            *reinterpret_cast<float4*>(out + (size_t)qb*COUT + c0) = res;
        }
    }
}

// ---------------------------------------------------------------------------
extern "C" void kernel_launch(void* const* d_in, const int* in_sizes, int n_in,
                              void* d_out, int out_size) {
    const float* x    = (const float*)d_in[0];
    const float* k1   = (const float*)d_in[1];
    const float* k2   = (const float*)d_in[2];
    const float* bias = (const float*)d_in[3];
    float* out = (float*)d_out;

    prep<<<VBLOCKS + WBLOCKS, 256>>>(x, k1, k2);
    morph_main<<<NPIX/4, 64>>>(bias, out);
}

// round 8
// speedup vs baseline: 1.0586x; 1.0586x over previous
#include <cuda_runtime.h>

#define N_IMG 8
#define H 32
#define W 32
#define CIN 32
#define COUT 64
#define HO 30
#define WO 30
#define NPIX (N_IMG*HO*WO)       // 7200
#define PDIM (3*3*CIN)           // 288

typedef unsigned long long u64;

// Scratch (device globals: no allocation allowed in kernel_launch)
// g_vq: per element {vx,vx,vy,vy} pre-splatted for f32x2 (16B/element, 4MB)
__device__ __align__(16) float4 g_vq[N_IMG*H*W*CIN];
__device__ __align__(16) float  g_ek1[PDIM*COUT];     // exp(k1), [p][cout]
__device__ __align__(16) float  g_ek2[PDIM*COUT];     // exp(k2), [p][cout]

#define NV4 (N_IMG*H*W*CIN/4)    // 65536 float4 elements of x
#define VBLOCKS (NV4/256)        // 256
#define WBLOCKS ((PDIM*COUT + 255)/256)  // 72

// packed multiply (f32x2), scalar max into two accumulators.
// mov.b64 unpack is register-pair aliasing; ptxas elides it.
__device__ __forceinline__ void mulmax(u64 v, u64 w, float& a0, float& a1) {
    float lo, hi;
    asm("{\n\t"
        ".reg .b64 t;\n\t"
        "mul.rn.f32x2 t, %2, %3;\n\t"
        "mov.b64 {%0, %1}, t;\n\t"
        "}" : "=f"(lo), "=f"(hi) : "l"(v), "l"(w));
    a0 = fmaxf(a0, lo);
    a1 = fmaxf(a1, hi);
}

// streaming (evict-first) 16B load: keeps the v stream out of L1's way
__device__ __forceinline__ ulonglong2 ldcs2(const ulonglong2* p) {
    ulonglong2 r;
    asm("ld.global.cs.v2.u64 {%0, %1}, [%2];" : "=l"(r.x), "=l"(r.y) : "l"(p));
    return r;
}

// ---------------------------------------------------------------------------
// Fused prep:
//   blocks [0,VBLOCKS):  per input float x -> float4 {vx,vx,vy,vy}
//   blocks [VBLOCKS, VBLOCKS+WBLOCKS): exp(weights)
// ---------------------------------------------------------------------------
__global__ void prep(const float* __restrict__ x,
                     const float* __restrict__ k1,
                     const float* __restrict__ k2) {
    const int b = blockIdx.x;
    if (b < VBLOCKS) {
        const int e4 = b*256 + threadIdx.x;          // float4 index into x
        const float4 xv = reinterpret_cast<const float4*>(x)[e4];
        float4* vp = g_vq + e4*4;
        const float a0 = fmaxf(xv.x, 0.1f), b0 = fmaxf(-xv.x, 0.1f);
        const float a1 = fmaxf(xv.y, 0.1f), b1 = fmaxf(-xv.y, 0.1f);
        const float a2 = fmaxf(xv.z, 0.1f), b2 = fmaxf(-xv.z, 0.1f);
        const float a3 = fmaxf(xv.w, 0.1f), b3 = fmaxf(-xv.w, 0.1f);
        vp[0] = make_float4(a0, a0, b0, b0);
        vp[1] = make_float4(a1, a1, b1, b1);
        vp[2] = make_float4(a2, a2, b2, b2);
        vp[3] = make_float4(a3, a3, b3, b3);
    } else {
        const int i = (b - VBLOCKS)*256 + threadIdx.x;
        if (i < PDIM*COUT) {
            g_ek1[i] = expf(k1[i]);
            g_ek2[i] = expf(k2[i]);
        }
    }
}

// ---------------------------------------------------------------------------
// Main: CTA = 96 threads = 3 warps, covering 2 pixels x 64 couts.
//   warp i owns kernel row i (96 k's); lane: cg = l&15 (4 couts), ps = l>>4.
// Per warp-iter: 1 LDG.128.cs (v quad, 2-addr broadcast) + 2 LDG.128 (w,
//   L1-resident) + 8 MUL.f32x2 + 16 FMNMX  -> ~28 slots / 32 results.
// Warps 1,2 publish partial maxes to smem; warp 0 combines + stores.
// ---------------------------------------------------------------------------
__global__ void __launch_bounds__(96, 10)
morph_main(const float* __restrict__ bias, float* __restrict__ out) {
    __shared__ float4 s_red[2][32][4];

    const int t    = threadIdx.x;
    const int lane = t & 31;
    const int wrp  = t >> 5;      // 0,1,2: kernel row i
    const int cg   = lane & 15;   // cout group (4 couts)
    const int ps   = lane >> 4;   // pixel slot 0/1
    const int c0   = cg * 4;

    const int q  = blockIdx.x*2 + ps;   // flat pixel 0..7199
    const int n  = q / (HO*WO);
    const int r  = q - n*(HO*WO);
    const int ho = r / WO;
    const int wo = r - ho*WO;

    // v quads for (ho+wrp, wo + 0..2, 0..31): 96 contiguous 16B elements
    const ulonglong2* __restrict__ vp =
        reinterpret_cast<const ulonglong2*>(g_vq) + ((n*H + ho + wrp)*W + wo)*CIN;
    // weight row = 64 floats = 16 ulonglong2; element cg; rows wrp*96 ..
    const ulonglong2* __restrict__ aw1 =
        reinterpret_cast<const ulonglong2*>(g_ek1) + cg + (wrp*96)*16;
    const ulonglong2* __restrict__ aw2 =
        reinterpret_cast<const ulonglong2*>(g_ek2) + cg + (wrp*96)*16;

    float m11[4], m12[4], m21[4], m22[4];
    #pragma unroll
    for (int k = 0; k < 4; k++) { m11[k]=0.f; m12[k]=0.f; m21[k]=0.f; m22[k]=0.f; }

    #pragma unroll 8
    for (int k = 0; k < 96; k++) {
        const ulonglong2 v  = ldcs2(vp + k);        // {vxx, vyy}
        const ulonglong2 w1 = __ldg(aw1 + k*16);
        const ulonglong2 w2 = __ldg(aw2 + k*16);
        mulmax(v.x, w1.x, m11[0], m11[1]);
        mulmax(v.x, w1.y, m11[2], m11[3]);
        mulmax(v.x, w2.x, m12[0], m12[1]);
        mulmax(v.x, w2.y, m12[2], m12[3]);
        mulmax(v.y, w1.x, m21[0], m21[1]);
        mulmax(v.y, w1.y, m21[2], m21[3]);
        mulmax(v.y, w2.x, m22[0], m22[1]);
        mulmax(v.y, w2.y, m22[2], m22[3]);
    }

    // 3-way cross-warp max-combine: warps 1,2 publish; warp 0 reduces+stores.
    if (wrp > 0) {
        s_red[wrp-1][lane][0] = make_float4(m11[0], m11[1], m11[2], m11[3]);
        s_red[wrp-1][lane][1] = make_float4(m12[0], m12[1], m12[2], m12[3]);
        s_red[wrp-1][lane][2] = make_float4(m21[0], m21[1], m21[2], m21[3]);
        s_red[wrp-1][lane][3] = make_float4(m22[0], m22[1], m22[2], m22[3]);
    }
    __syncthreads();
    if (wrp == 0) {
        #pragma unroll
        for (int w = 0; w < 2; w++) {
            const float4 o11 = s_red[w][lane][0], o12 = s_red[w][lane][1];
            const float4 o21 = s_red[w][lane][2], o22 = s_red[w][lane][3];
            m11[0] = fmaxf(m11[0], o11.x); m11[1] = fmaxf(m11[1], o11.y);
            m11[2] = fmaxf(m11[2], o11.z); m11[3] = fmaxf(m11[3], o11.w);
            m12[0] = fmaxf(m12[0], o12.x); m12[1] = fmaxf(m12[1], o12.y);
            m12[2] = fmaxf(m12[2], o12.z); m12[3] = fmaxf(m12[3], o12.w);
            m21[0] = fmaxf(m21[0], o21.x); m21[1] = fmaxf(m21[1], o21.y);
            m21[2] = fmaxf(m21[2], o21.z); m21[3] = fmaxf(m21[3], o21.w);
            m22[0] = fmaxf(m22[0], o22.x); m22[1] = fmaxf(m22[1], o22.y);
            m22[2] = fmaxf(m22[2], o22.z); m22[3] = fmaxf(m22[3], o22.w);
        }

        const float4 bv = *reinterpret_cast<const float4*>(bias + c0);
        float4 res;
        res.x = m11[0] - m12[0] - m21[0] + m22[0] + bv.x;
        res.y = m11[1] - m12[1] - m21[1] + m22[1] + bv.y;
        res.z = m11[2] - m12[2] - m21[2] + m22[2] + bv.z;
        res.w = m11[3] - m12[3] - m21[3] + m22[3] + bv.w;

        *reinterpret_cast<float4*>(out + (size_t)q*COUT + c0) = res;
    }
}

// ---------------------------------------------------------------------------
extern "C" void kernel_launch(void* const* d_in, const int* in_sizes, int n_in,
                              void* d_out, int out_size) {
    const float* x    = (const float*)d_in[0];
    const float* k1   = (const float*)d_in[1];
    const float* k2   = (const float*)d_in[2];
    const float* bias = (const float*)d_in[3];
    float* out = (float*)d_out;

    prep<<<VBLOCKS + WBLOCKS, 256>>>(x, k1, k2);
    morph_main<<<NPIX/2, 96>>>(bias, out);
}